// round 10
// baseline (speedup 1.0000x reference)
#include <cuda_runtime.h>
#include <math.h>

#define NT 256
#define RPB 8
#define NBLK 128
#define CLUSTER 8

typedef unsigned long long ull;

// ---------------- device scratch ----------------
__device__ float g_W0cs[8 * 152 * 64];   // [cr][k][c], c = ulocal*4 + gate
__device__ float g_W1cs[8 * 256 * 64];   // [cr][k][c]
__device__ float g_b0cs[8 * 64];
__device__ float g_b1cs[8 * 64];
__device__ float g_W1T[184 * 128];       // [k][u]  (diffusion)
__device__ float g_W2s[128 * 128];       // [u][v] = W2[v][u]
__device__ float g_A1t[100 * 128];
__device__ float g_cy[100];
__device__ float g_ce[100];
__device__ float g_enc[1024 * 128];      // [dblock(8 rows)][128 u][8 r]

// ---------------- prologue ----------------
__global__ void prologue_kernel(const float* __restrict__ W_ih0, const float* __restrict__ W_hh0,
                                const float* __restrict__ b_ih0, const float* __restrict__ b_hh0,
                                const float* __restrict__ W_ih1, const float* __restrict__ W_hh1,
                                const float* __restrict__ b_ih1, const float* __restrict__ b_hh1,
                                const float* __restrict__ W1,    const float* __restrict__ W2) {
    int tid = blockIdx.x * blockDim.x + threadIdx.x;
    int nth = gridDim.x * blockDim.x;

    for (int i = tid; i < 8 * 152 * 64; i += nth) {
        int cr = i / (152 * 64);
        int rem = i % (152 * 64);
        int k = rem >> 6, c = rem & 63;
        int ul = c >> 2, g = c & 3;
        int grow = g * 128 + cr * 16 + ul;
        g_W0cs[i] = (k < 24) ? W_ih0[grow * 24 + k] : W_hh0[grow * 128 + (k - 24)];
    }
    for (int i = tid; i < 8 * 256 * 64; i += nth) {
        int cr = i / (256 * 64);
        int rem = i % (256 * 64);
        int k = rem >> 6, c = rem & 63;
        int ul = c >> 2, g = c & 3;
        int grow = g * 128 + cr * 16 + ul;
        g_W1cs[i] = (k < 128) ? W_ih1[grow * 128 + k] : W_hh1[grow * 128 + (k - 128)];
    }
    for (int i = tid; i < 512; i += nth) {
        int cr = i >> 6, c = i & 63;
        int ul = c >> 2, g = c & 3;
        int grow = g * 128 + cr * 16 + ul;
        g_b0cs[i] = b_ih0[grow] + b_hh0[grow];
        g_b1cs[i] = b_ih1[grow] + b_hh1[grow];
    }
    for (int i = tid; i < 184 * 128; i += nth) {
        int k = i >> 7, u = i & 127;
        g_W1T[i] = W1[u * 184 + k];
    }
    for (int i = tid; i < 128 * 128; i += nth) {
        int u = i >> 7, v = i & 127;
        g_W2s[i] = W2[v * 128 + u];
    }
    for (int i = tid; i < 100 * 128; i += nth) {
        int t = i >> 7, u = i & 127;
        float acc = 0.f;
        #pragma unroll
        for (int j = 0; j < 8; j++) {
            float f = expf(-logf(10000.0f) * (float)j / 8.0f);
            float a = (float)t * f;
            acc += W1[u * 184 + 152 + j] * cosf(a);
            acc += W1[u * 184 + 160 + j] * sinf(a);
        }
        g_A1t[i] = acc;
    }
    if (tid == 0) {
        float ab = 1.0f;
        for (int t = 0; t < 100; t++) {
            float beta  = 1e-4f + (0.02f - 1e-4f) * (float)t / 99.0f;
            float alpha = 1.0f - beta;
            ab *= alpha;
            if (t == 0) {
                float p = sqrtf(ab) + 1e-8f;
                g_cy[0] = 1.0f / p;
                g_ce[0] = sqrtf(1.0f - ab) / p;
            } else {
                float inv = 1.0f / (sqrtf(alpha) + 1e-8f);
                g_cy[t] = inv;
                g_ce[t] = beta / (sqrtf(1.0f - ab) + 1e-8f) * inv;
            }
        }
    }
}

// ---------------- fast math helpers ----------------
__device__ __forceinline__ float sigf(float x) {
    float xc = fminf(fmaxf(x, -30.f), 30.f);
    return __fdividef(1.0f, 1.0f + __expf(-xc));
}
__device__ __forceinline__ float tanhf_fast(float x) {
    float xc = fminf(fmaxf(x, -15.f), 15.f);
    float e = __expf(2.0f * xc);
    return __fdividef(e - 1.0f, e + 1.0f);
}
__device__ __forceinline__ void ffma2(ull &d, ull a, ull b) {
    asm("fma.rn.f32x2 %0, %1, %2, %0;" : "+l"(d) : "l"(a), "l"(b));
}
__device__ __forceinline__ ull dup2(float x) {
    ull r;
    asm("mov.b64 %0, {%1, %1};" : "=l"(r) : "f"(x));
    return r;
}
__device__ __forceinline__ ull pack2(float lo, float hi) {
    ull r;
    asm("mov.b64 %0, {%1, %2};" : "=l"(r) : "f"(lo), "f"(hi));
    return r;
}
__device__ __forceinline__ float2 unpack2(ull v) {
    float2 r;
    asm("mov.b64 {%0, %1}, %2;" : "=f"(r.x), "=f"(r.y) : "l"(v));
    return r;
}
__device__ __forceinline__ unsigned smem_u32(const void* p) {
    unsigned a;
    asm("{ .reg .u64 t; cvta.to.shared.u64 t, %1; cvt.u32.u64 %0, t; }" : "=r"(a) : "l"(p));
    return a;
}

#define CLUSTER_SYNC() do { \
    asm volatile("barrier.cluster.arrive.aligned;" ::: "memory"); \
    asm volatile("barrier.cluster.wait.aligned;" ::: "memory"); \
} while (0)

// broadcast a float4 to the same smem offset in all 8 cluster CTAs
__device__ __forceinline__ void bcast_store_f4(unsigned laddr, float4 v) {
    #pragma unroll
    for (int p = 0; p < CLUSTER; p++) {
        unsigned ra;
        asm("mapa.shared::cluster.u32 %0, %1, %2;" : "=r"(ra) : "r"(laddr), "r"(p));
        asm volatile("st.shared::cluster.v4.f32 [%0], {%1, %2, %3, %4};"
                     :: "r"(ra), "f"(v.x), "f"(v.y), "f"(v.z), "f"(v.w) : "memory");
    }
}

// ---------------- LSTM smem layout (floats) ----------------
// xv pitch = 68 floats per feature-row (64 rows + pad; 16B-aligned, conflict-light)
#define LW0   0                    // 152*64 = 9728
#define LW1   9728                 // 256*64 = 16384
#define LXV   26112                // 280*68 = 19040
#define LTOT  45152
#define LSTM_SMEM_BYTES (LTOT * 4) // 180,608 B

// GEMM: thread (u = tid&15, rg4 = 4*(tid>>4)); 4 gate-cols x 4 rows in registers
__device__ __forceinline__ void gemm_acc(const float* __restrict__ wsm,
                                         const float* __restrict__ xbase, int K,
                                         int u4, int rg4, ull acc[4][2]) {
    #pragma unroll 8
    for (int k = 0; k < K; k++) {
        const ulonglong2 wp = *reinterpret_cast<const ulonglong2*>(wsm + (k << 6) + u4);
        const float4 x = *reinterpret_cast<const float4*>(xbase + k * 68 + rg4);
        ull d0 = dup2(x.x), d1 = dup2(x.y), d2 = dup2(x.z), d3 = dup2(x.w);
        ffma2(acc[0][0], wp.x, d0); ffma2(acc[0][1], wp.y, d0);
        ffma2(acc[1][0], wp.x, d1); ffma2(acc[1][1], wp.y, d1);
        ffma2(acc[2][0], wp.x, d2); ffma2(acc[2][1], wp.y, d2);
        ffma2(acc[3][0], wp.x, d3); ffma2(acc[3][1], wp.y, d3);
    }
}

// =====================================================================
// Kernel 1: LSTM encoder — 8-CTA cluster, persistent weights in smem
// =====================================================================
__global__ __launch_bounds__(NT, 1) __cluster_dims__(CLUSTER, 1, 1)
void lstm_kernel(const float* __restrict__ x_hist, const int* __restrict__ turb_idx,
                 const float* __restrict__ turb_emb) {
    extern __shared__ float sm[];
    float* w0s = sm + LW0;
    float* w1s = sm + LW1;
    float* xv  = sm + LXV;

    const int tid = threadIdx.x;
    unsigned cr;
    asm("mov.u32 %0, %%cluster_ctarank;" : "=r"(cr));
    const int cl = blockIdx.x >> 3;
    const int browc = cl * 64;

    // ---- one-time init ----
    // persistent weight slice via cp.async
    {
        unsigned s0 = smem_u32(w0s);
        const float* g0 = g_W0cs + (int)cr * 152 * 64;
        for (int i = tid; i < 2432; i += NT)
            asm volatile("cp.async.cg.shared.global [%0], [%1], 16;\n"
                         :: "r"(s0 + i * 16), "l"(g0 + i * 4));
        unsigned s1 = smem_u32(w1s);
        const float* g1 = g_W1cs + (int)cr * 256 * 64;
        for (int i = tid; i < 4096; i += NT)
            asm volatile("cp.async.cg.shared.global [%0], [%1], 16;\n"
                         :: "r"(s1 + i * 16), "l"(g1 + i * 4));
        asm volatile("cp.async.commit_group;\n" ::: "memory");
    }
    // zero h0/h1 region (rows 24..279)
    for (int i = tid; i < 256 * 68; i += NT) xv[24 * 68 + i] = 0.0f;
    // emb rows 8..23
    for (int i = tid; i < 16 * 64; i += NT) {
        int k = i >> 6, r = i & 63;
        xv[(8 + k) * 68 + r] = turb_emb[turb_idx[browc + r] * 16 + k];
    }
    // x rows 0..7 for t=0
    for (int i = tid; i < 512; i += NT) {
        int k = i & 7, r = i >> 3;
        xv[k * 68 + r] = x_hist[((browc + r) * 96 + 0) * 8 + k];
    }
    asm volatile("cp.async.wait_group 0;\n" ::: "memory");
    __syncthreads();

    const int u   = tid & 15;
    const int u4  = u << 2;
    const int rg4 = (tid >> 4) << 2;

    const float4 b0r = *reinterpret_cast<const float4*>(g_b0cs + (int)cr * 64 + u4);
    const float4 b1r = *reinterpret_cast<const float4*>(g_b1cs + (int)cr * 64 + u4);

    const unsigned xvb = smem_u32(xv);
    const unsigned laddr0 = xvb + (unsigned)(((24  + (int)cr * 16 + u) * 68 + rg4) * 4);
    const unsigned laddr1 = xvb + (unsigned)(((152 + (int)cr * 16 + u) * 68 + rg4) * 4);

    float c0r[4] = {0.f, 0.f, 0.f, 0.f};
    float c1r[4] = {0.f, 0.f, 0.f, 0.f};

    for (int t = 0; t < 96; t++) {
        // ---- layer 0 GEMM (reads x/emb/h0_prev) ----
        ull acc[4][2];
        acc[0][0]=acc[0][1]=acc[1][0]=acc[1][1]=acc[2][0]=acc[2][1]=acc[3][0]=acc[3][1]=0ULL;
        gemm_acc(w0s, xv, 152, u4, rg4, acc);
        CLUSTER_SYNC();   // S1: everyone finished reading h0_prev + x_t

        // prefetch x_{t+1}
        float xp0 = 0.f, xp1 = 0.f;
        if (t + 1 < 96) {
            int i0 = tid, i1 = tid + 256;
            xp0 = __ldg(&x_hist[((browc + (i0 >> 3)) * 96 + t + 1) * 8 + (i0 & 7)]);
            xp1 = __ldg(&x_hist[((browc + (i1 >> 3)) * 96 + t + 1) * 8 + (i1 & 7)]);
        }

        // ---- combine layer 0 (registers) + broadcast h0 ----
        {
            float h[4];
            #pragma unroll
            for (int r = 0; r < 4; r++) {
                float2 p0 = unpack2(acc[r][0]);   // (i, f)
                float2 p1 = unpack2(acc[r][1]);   // (g, o)
                float gi = p0.x + b0r.x, gf = p0.y + b0r.y;
                float gg = p1.x + b0r.z, go = p1.y + b0r.w;
                float cc = sigf(gf) * c0r[r] + sigf(gi) * tanhf_fast(gg);
                c0r[r] = cc;
                h[r] = sigf(go) * tanhf_fast(cc);
            }
            bcast_store_f4(laddr0, make_float4(h[0], h[1], h[2], h[3]));
        }
        // store x_{t+1} (local rows 0..7)
        if (t + 1 < 96) {
            int i0 = tid, i1 = tid + 256;
            xv[(i0 & 7) * 68 + (i0 >> 3)] = xp0;
            xv[(i1 & 7) * 68 + (i1 >> 3)] = xp1;
        }
        CLUSTER_SYNC();   // S2: h0_new visible in all replicas

        // ---- layer 1 GEMM (reads h0_new + h1_prev) ----
        acc[0][0]=acc[0][1]=acc[1][0]=acc[1][1]=acc[2][0]=acc[2][1]=acc[3][0]=acc[3][1]=0ULL;
        gemm_acc(w1s, xv + 24 * 68, 256, u4, rg4, acc);
        CLUSTER_SYNC();   // S3: everyone finished reading h1_prev

        // ---- combine layer 1 + broadcast h1 ----
        {
            float h[4];
            #pragma unroll
            for (int r = 0; r < 4; r++) {
                float2 p0 = unpack2(acc[r][0]);
                float2 p1 = unpack2(acc[r][1]);
                float gi = p0.x + b1r.x, gf = p0.y + b1r.y;
                float gg = p1.x + b1r.z, go = p1.y + b1r.w;
                float cc = sigf(gf) * c1r[r] + sigf(gi) * tanhf_fast(gg);
                c1r[r] = cc;
                h[r] = sigf(go) * tanhf_fast(cc);
            }
            bcast_store_f4(laddr1, make_float4(h[0], h[1], h[2], h[3]));
        }
        // next iteration's S1/S2 order h1_new before the next L1 read
    }
    CLUSTER_SYNC();   // final h1 delivered everywhere

    // write enc_out: this CTA handles dblock = cl*8 + cr (local rows 8cr..8cr+7)
    {
        const int dblock = cl * 8 + (int)cr;
        for (int i = tid; i < 1024; i += NT) {
            int uo = i >> 3, j = i & 7;
            g_enc[dblock * 1024 + i] = xv[(152 + uo) * 68 + (int)cr * 8 + j];
        }
    }
}

// =====================================================================
// Diffusion kernel (unchanged from R9)
// =====================================================================
#define DS_ENC    0        // [128 u][8 r]
#define DS_MH1    1024
#define DS_A1     2048     // 12800
#define DS_W1Y    14848
#define DS_W3     14976
#define DS_BM2    15104
#define DS_EMBT   15232
#define DS_XFT    15360
#define DS_HES    15408
#define DS_CY     15440
#define DS_CE     15540
#define DS_RED    15640
#define DS_TOTAL  15672
#define DIFF_SMEM_BYTES (DS_TOTAL * 4)

__device__ __forceinline__ void barh(int half) {
    asm volatile("bar.sync %0, 128;" :: "r"(half + 1) : "memory");
}

__global__ __launch_bounds__(NT, 1)
void diffusion_kernel(const float* __restrict__ x_future, const float* __restrict__ y0,
                      const int* __restrict__ turb_idx, const float* __restrict__ init_noise,
                      const float* __restrict__ turb_emb,
                      const float* __restrict__ b1m, const float* __restrict__ b2m,
                      const float* __restrict__ W3, const float* __restrict__ b3p,
                      float* __restrict__ out) {
    extern __shared__ float sm[];
    float* encs  = sm + DS_ENC;
    float* mh1   = sm + DS_MH1;
    float* a1s   = sm + DS_A1;
    float* w1ys  = sm + DS_W1Y;
    float* w3s   = sm + DS_W3;
    float* bm2s  = sm + DS_BM2;
    float* embT  = sm + DS_EMBT;
    float* xfT   = sm + DS_XFT;
    float* hes   = sm + DS_HES;
    float* cys   = sm + DS_CY;
    float* ces   = sm + DS_CE;
    float* red   = sm + DS_RED;

    const int tid  = threadIdx.x;
    const int brow = blockIdx.x * RPB;

    for (int i = tid; i < 12800; i += NT) a1s[i] = g_A1t[i];
    {
        float4* src = reinterpret_cast<float4*>(g_enc + blockIdx.x * 1024);
        float4* dst = reinterpret_cast<float4*>(encs);
        if (tid < 256) dst[tid] = src[tid];
    }
    if (tid < 128) {
        int k = tid >> 3, r = tid & 7;
        embT[k * 8 + r] = turb_emb[turb_idx[brow + r] * 16 + k];
        w1ys[tid] = g_W1T[151 * 128 + tid];
        w3s[tid]  = W3[tid];
        bm2s[tid] = b2m[tid];
    }
    if (tid < 100) { cys[tid] = g_cy[tid]; ces[tid] = g_ce[tid]; }
    __syncthreads();

    const int uu   = tid & 127;
    const int half = tid >> 7;
    const int local = tid & 127;
    const int r0d = half * 4;
    const float b3v = __ldg(&b3p[0]);

    float w2r[128];
    #pragma unroll
    for (int u = 0; u < 128; u++) w2r[u] = __ldg(&g_W2s[(u << 7) + uu]);

    const float w1yv = w1ys[uu];
    const float w3v  = w3s[uu];
    const float bm2v = bm2s[uu];
    const ull bm2p = pack2(bm2v, bm2v);

    float ypa[4];
    #pragma unroll
    for (int j = 0; j < 4; j++) ypa[j] = __ldg(&y0[brow + r0d + j]);

    const int wih = (tid >> 5) & 3;
    const int lane = tid & 31;

    for (int p = 0; p < 8; p++) {
        if (local < 24) {
            int k = local >> 2, rl = local & 3;
            xfT[half * 24 + k * 4 + rl] = __ldg(&x_future[(brow + r0d + rl) * 48 + p * 6 + k]);
        }
        if (local < 16) {
            int j = local & 7;
            float f = __expf(-logf(10000.0f) * (float)j / 8.0f);
            float a = (float)p * f;
            hes[half * 16 + local] = (local < 8) ? cosf(a) : sinf(a);
        }
        float yra[4];
        #pragma unroll
        for (int j = 0; j < 4; j++) yra[j] = __ldg(&init_noise[p * 1024 + brow + r0d + j]);
        barh(half);

        float4 base = make_float4(0.f, 0.f, 0.f, 0.f);
        {
            #pragma unroll 8
            for (int k = 0; k < 128; k++) {
                float w = __ldg(&g_W1T[(k << 7) + uu]);
                const float4 h = *reinterpret_cast<const float4*>(&encs[k * 8 + r0d]);
                base.x += w * h.x; base.y += w * h.y; base.z += w * h.z; base.w += w * h.w;
            }
            #pragma unroll
            for (int k = 0; k < 6; k++) {
                float w = __ldg(&g_W1T[((128 + k) << 7) + uu]);
                const float4 x = *reinterpret_cast<const float4*>(&xfT[half * 24 + k * 4]);
                base.x += w * x.x; base.y += w * x.y; base.z += w * x.z; base.w += w * x.w;
            }
            #pragma unroll
            for (int k = 0; k < 16; k++) {
                float w = __ldg(&g_W1T[((134 + k) << 7) + uu]);
                const float* ep = &embT[k * 8 + r0d];
                base.x += w * ep[0]; base.y += w * ep[1]; base.z += w * ep[2]; base.w += w * ep[3];
            }
            {
                float w = __ldg(&g_W1T[(150 << 7) + uu]);
                base.x += w * ypa[0]; base.y += w * ypa[1]; base.z += w * ypa[2]; base.w += w * ypa[3];
            }
            float hsum = 0.f;
            #pragma unroll
            for (int k = 0; k < 16; k++) hsum += __ldg(&g_W1T[((168 + k) << 7) + uu]) * hes[half * 16 + k];
            float bb = __ldg(&b1m[uu]) + hsum;
            base.x += bb; base.y += bb; base.z += bb; base.w += bb;
        }

        for (int tt = 99; tt >= 0; tt--) {
            {
                float av = a1s[tt * 128 + uu];
                float4 m;
                m.x = fmaxf(base.x + yra[0] * w1yv + av, 0.f);
                m.y = fmaxf(base.y + yra[1] * w1yv + av, 0.f);
                m.z = fmaxf(base.z + yra[2] * w1yv + av, 0.f);
                m.w = fmaxf(base.w + yra[3] * w1yv + av, 0.f);
                *reinterpret_cast<float4*>(&mh1[(uu << 3) + r0d]) = m;
            }
            barh(half);

            {
                ull acc01 = bm2p;
                ull acc23 = bm2p;
                #pragma unroll
                for (int u = 0; u < 128; u++) {
                    const ulonglong2 h = *reinterpret_cast<const ulonglong2*>(&mh1[(u << 3) + r0d]);
                    ull dw = dup2(w2r[u]);
                    ffma2(acc01, dw, h.x);
                    ffma2(acc23, dw, h.y);
                }
                float2 a01 = unpack2(acc01);
                float2 a23 = unpack2(acc23);
                float e0 = fmaxf(a01.x, 0.f) * w3v;
                float e1 = fmaxf(a01.y, 0.f) * w3v;
                float e2 = fmaxf(a23.x, 0.f) * w3v;
                float e3 = fmaxf(a23.y, 0.f) * w3v;
                #pragma unroll
                for (int off = 16; off > 0; off >>= 1) {
                    e0 += __shfl_down_sync(0xffffffffu, e0, off);
                    e1 += __shfl_down_sync(0xffffffffu, e1, off);
                    e2 += __shfl_down_sync(0xffffffffu, e2, off);
                    e3 += __shfl_down_sync(0xffffffffu, e3, off);
                }
                if (lane == 0)
                    *reinterpret_cast<float4*>(&red[half * 16 + wih * 4]) = make_float4(e0, e1, e2, e3);
            }
            barh(half);

            {
                const float4 q0 = *reinterpret_cast<const float4*>(&red[half * 16 + 0]);
                const float4 q1 = *reinterpret_cast<const float4*>(&red[half * 16 + 4]);
                const float4 q2 = *reinterpret_cast<const float4*>(&red[half * 16 + 8]);
                const float4 q3 = *reinterpret_cast<const float4*>(&red[half * 16 + 12]);
                float cy = cys[tt], ce = ces[tt];
                yra[0] = cy * yra[0] - ce * (b3v + q0.x + q1.x + q2.x + q3.x);
                yra[1] = cy * yra[1] - ce * (b3v + q0.y + q1.y + q2.y + q3.y);
                yra[2] = cy * yra[2] - ce * (b3v + q0.z + q1.z + q2.z + q3.z);
                yra[3] = cy * yra[3] - ce * (b3v + q0.w + q1.w + q2.w + q3.w);
            }
        }

        if (local < 4) {
            float v = (local == 0) ? yra[0] : (local == 1) ? yra[1] : (local == 2) ? yra[2] : yra[3];
            out[(brow + r0d + local) * 8 + p] = v;
        }
        #pragma unroll
        for (int j = 0; j < 4; j++) ypa[j] = yra[j];
    }
}

// ---------------- launch ----------------
extern "C" void kernel_launch(void* const* d_in, const int* in_sizes, int n_in,
                              void* d_out, int out_size) {
    const float* x_hist     = (const float*)d_in[0];
    const float* x_future   = (const float*)d_in[1];
    const float* y0         = (const float*)d_in[2];
    const int*   turb_idx   = (const int*)d_in[3];
    const float* init_noise = (const float*)d_in[5];
    const float* turb_emb   = (const float*)d_in[6];
    const float* W_ih0      = (const float*)d_in[7];
    const float* W_hh0      = (const float*)d_in[8];
    const float* b_ih0      = (const float*)d_in[9];
    const float* b_hh0      = (const float*)d_in[10];
    const float* W_ih1      = (const float*)d_in[11];
    const float* W_hh1      = (const float*)d_in[12];
    const float* b_ih1      = (const float*)d_in[13];
    const float* b_hh1      = (const float*)d_in[14];
    const float* W1         = (const float*)d_in[15];
    const float* b1m        = (const float*)d_in[16];
    const float* W2         = (const float*)d_in[17];
    const float* b2m        = (const float*)d_in[18];
    const float* W3         = (const float*)d_in[19];
    const float* b3         = (const float*)d_in[20];
    float* out = (float*)d_out;

    prologue_kernel<<<128, 256>>>(W_ih0, W_hh0, b_ih0, b_hh0,
                                  W_ih1, W_hh1, b_ih1, b_hh1, W1, W2);

    cudaFuncSetAttribute(lstm_kernel, cudaFuncAttributeMaxDynamicSharedMemorySize, LSTM_SMEM_BYTES);
    lstm_kernel<<<NBLK, NT, LSTM_SMEM_BYTES>>>(x_hist, turb_idx, turb_emb);

    cudaFuncSetAttribute(diffusion_kernel, cudaFuncAttributeMaxDynamicSharedMemorySize, DIFF_SMEM_BYTES);
    diffusion_kernel<<<NBLK, NT, DIFF_SMEM_BYTES>>>(x_future, y0, turb_idx, init_noise,
                                                    turb_emb, b1m, b2m, W3, b3, out);
}

// round 11
// speedup vs baseline: 1.6635x; 1.6635x over previous
#include <cuda_runtime.h>
#include <math.h>

#define NT 256
#define RPB 8
#define NBLK 128
#define KC 32

typedef unsigned long long ull;

// ---------------- device scratch ----------------
__device__ float g_W0cat[152 * 512];   // [k][g]: rows 0..23 Wih0^T, 24..151 Whh0^T
__device__ float g_W1cat[256 * 512];   // [k][g]: rows 0..127 Wih1^T, 128..255 Whh1^T
__device__ float g_b0[512];
__device__ float g_b1[512];
__device__ float g_W1T[184 * 128];     // [k][u]
__device__ float g_W2s[128 * 128];     // [u][v] = W2[v][u]
__device__ float g_A1t[100 * 128];
__device__ float g_cy[100];
__device__ float g_ce[100];

// ---------------- prologue ----------------
__global__ void prologue_kernel(const float* __restrict__ W_ih0, const float* __restrict__ W_hh0,
                                const float* __restrict__ b_ih0, const float* __restrict__ b_hh0,
                                const float* __restrict__ W_ih1, const float* __restrict__ W_hh1,
                                const float* __restrict__ b_ih1, const float* __restrict__ b_hh1,
                                const float* __restrict__ W1,    const float* __restrict__ W2) {
    int tid = blockIdx.x * blockDim.x + threadIdx.x;
    int nth = gridDim.x * blockDim.x;

    for (int i = tid; i < 24 * 512; i += nth) {
        int k = i >> 9, g = i & 511;
        g_W0cat[i] = W_ih0[g * 24 + k];
    }
    for (int i = tid; i < 128 * 512; i += nth) {
        int k = i >> 9, g = i & 511;
        g_W0cat[(24 + k) * 512 + g]  = W_hh0[g * 128 + k];
        g_W1cat[k * 512 + g]         = W_ih1[g * 128 + k];
        g_W1cat[(128 + k) * 512 + g] = W_hh1[g * 128 + k];
    }
    for (int i = tid; i < 512; i += nth) {
        g_b0[i] = b_ih0[i] + b_hh0[i];
        g_b1[i] = b_ih1[i] + b_hh1[i];
    }
    for (int i = tid; i < 184 * 128; i += nth) {
        int k = i >> 7, u = i & 127;
        g_W1T[i] = W1[u * 184 + k];
    }
    for (int i = tid; i < 128 * 128; i += nth) {
        int u = i >> 7, v = i & 127;
        g_W2s[i] = W2[v * 128 + u];
    }
    for (int i = tid; i < 100 * 128; i += nth) {
        int t = i >> 7, u = i & 127;
        float acc = 0.f;
        #pragma unroll
        for (int j = 0; j < 8; j++) {
            float f = expf(-logf(10000.0f) * (float)j / 8.0f);
            float a = (float)t * f;
            acc += W1[u * 184 + 152 + j] * cosf(a);
            acc += W1[u * 184 + 160 + j] * sinf(a);
        }
        g_A1t[i] = acc;
    }
    if (tid == 0) {
        float ab = 1.0f;
        for (int t = 0; t < 100; t++) {
            float beta  = 1e-4f + (0.02f - 1e-4f) * (float)t / 99.0f;
            float alpha = 1.0f - beta;
            ab *= alpha;
            if (t == 0) {
                float p = sqrtf(ab) + 1e-8f;
                g_cy[0] = 1.0f / p;
                g_ce[0] = sqrtf(1.0f - ab) / p;
            } else {
                float inv = 1.0f / (sqrtf(alpha) + 1e-8f);
                g_cy[t] = inv;
                g_ce[t] = beta / (sqrtf(1.0f - ab) + 1e-8f) * inv;
            }
        }
    }
}

// ---------------- fast math helpers ----------------
__device__ __forceinline__ float sigf(float x) {
    float xc = fminf(fmaxf(x, -30.f), 30.f);
    return __fdividef(1.0f, 1.0f + __expf(-xc));
}
__device__ __forceinline__ float tanhf_fast(float x) {
    float xc = fminf(fmaxf(x, -15.f), 15.f);
    float e = __expf(2.0f * xc);
    return __fdividef(e - 1.0f, e + 1.0f);
}
__device__ __forceinline__ void ffma2(ull &d, ull a, ull b) {
    asm("fma.rn.f32x2 %0, %1, %2, %0;" : "+l"(d) : "l"(a), "l"(b));
}
__device__ __forceinline__ ull dup2(float x) {
    ull r;
    asm("mov.b64 %0, {%1, %1};" : "=l"(r) : "f"(x));
    return r;
}
__device__ __forceinline__ ull pack2(float lo, float hi) {
    ull r;
    asm("mov.b64 %0, {%1, %2};" : "=l"(r) : "f"(lo), "f"(hi));
    return r;
}
__device__ __forceinline__ float2 unpack2(ull v) {
    float2 r;
    asm("mov.b64 {%0, %1}, %2;" : "=f"(r.x), "=f"(r.y) : "l"(v));
    return r;
}

// ---------------- smem layout (floats) ----------------
#define SM_XV     0        // [280][8]: rows 0..7 x_t, 8..23 emb, 24..151 h0, 152..279 h1
#define SM_GATES  2240     // [8][512]
#define SM_STAGE  6336     // 2 x (KC*512) = 32768
#define SM_B0     39104    // 512
#define SM_B1     39616    // 512
#define SM_EMBR   40128    // [8][16]
#define SM_EMBT   40256    // [16][8]
#define SM_MH1    40384    // [128][8]
#define SM_W1Y    41408    // 128
#define SM_W3     41536    // 128
#define SM_BM2    41664    // 128
#define SM_XFT    41792    // 48
#define SM_HES    41840    // 32
#define SM_CY     41872    // 100
#define SM_CE     41972    // 100
#define SM_RED    42072    // 32
#define SM_A1     42112    // 12800
#define SM_TOTAL  54912
#define SMEM_BYTES (SM_TOTAL * 4)

// ---------------- staging helper ----------------
__device__ __forceinline__ void stage_chunk(float* sdst, const float* __restrict__ gsrc, int nf4) {
    unsigned sbase = (unsigned)__cvta_generic_to_shared(sdst);
    for (int i = threadIdx.x; i < nf4; i += NT) {
        asm volatile("cp.async.cg.shared.global [%0], [%1], 16;\n"
                     :: "r"(sbase + i * 16), "l"(gsrc + i * 4));
    }
    asm volatile("cp.async.commit_group;\n" ::: "memory");
}

__device__ __forceinline__ void barh(int half) {
    asm volatile("bar.sync %0, 128;" :: "r"(half + 1) : "memory");
}

// ---------------- LSTM GEMM: single sync per chunk (wait -> sync -> stage next -> compute) ----------------
// NOTE: no trailing sync — the CALLER must __syncthreads() before reading gates.
__device__ __forceinline__ void lstm_gemm(const float* __restrict__ gW, int K,
                                          const float* __restrict__ xv, float* gates,
                                          float* stg, int g0, int r0g) {
    ull a00 = 0, a01 = 0, a10 = 0, a11 = 0, a20 = 0, a21 = 0, a30 = 0, a31 = 0;

    const int NC = (K + KC - 1) / KC;
    {
        int kc0 = (K < KC) ? K : KC;
        stage_chunk(stg, gW, kc0 * 128);   // chunk 0 -> buf0
    }

    for (int c = 0; c < NC; c++) {
        asm volatile("cp.async.wait_group 0;\n" ::: "memory");
        __syncthreads();   // chunk c staged AND all threads finished compute of c-1

        // stage chunk c+1 into the buffer last used by chunk c-1 (safe after the sync)
        if (c + 1 < NC) {
            int kn = K - (c + 1) * KC; if (kn > KC) kn = KC;
            stage_chunk(stg + ((c + 1) & 1) * (KC * 512), gW + (c + 1) * KC * 512, kn * 128);
        }

        const float* buf = stg + (c & 1) * (KC * 512);
        const int kbase = c * KC;
        int kc = K - kbase; if (kc > KC) kc = KC;

        #pragma unroll 8
        for (int kk = 0; kk < kc; kk++) {
            const ulonglong2 w = *reinterpret_cast<const ulonglong2*>(buf + (kk << 9) + g0);
            const float4 x = *reinterpret_cast<const float4*>(xv + ((kbase + kk) << 3) + r0g);
            ull d0 = dup2(x.x), d1 = dup2(x.y), d2 = dup2(x.z), d3 = dup2(x.w);
            ffma2(a00, w.x, d0); ffma2(a01, w.y, d0);
            ffma2(a10, w.x, d1); ffma2(a11, w.y, d1);
            ffma2(a20, w.x, d2); ffma2(a21, w.y, d2);
            ffma2(a30, w.x, d3); ffma2(a31, w.y, d3);
        }

        if (c == NC - 1) {
            *reinterpret_cast<ulonglong2*>(&gates[(r0g    ) * 512 + g0]) = make_ulonglong2(a00, a01);
            *reinterpret_cast<ulonglong2*>(&gates[(r0g + 1) * 512 + g0]) = make_ulonglong2(a10, a11);
            *reinterpret_cast<ulonglong2*>(&gates[(r0g + 2) * 512 + g0]) = make_ulonglong2(a20, a21);
            *reinterpret_cast<ulonglong2*>(&gates[(r0g + 3) * 512 + g0]) = make_ulonglong2(a30, a31);
        }
    }
}

// ---------------- main fused kernel ----------------
__global__ __launch_bounds__(NT, 1)
void fused_kernel(const float* __restrict__ x_hist, const float* __restrict__ x_future,
                  const float* __restrict__ y0, const int* __restrict__ turb_idx,
                  const float* __restrict__ init_noise, const float* __restrict__ turb_emb,
                  const float* __restrict__ b1m, const float* __restrict__ b2m,
                  const float* __restrict__ W3, const float* __restrict__ b3p,
                  float* __restrict__ out) {
    extern __shared__ float sm[];
    float* xv    = sm + SM_XV;
    float* gates = sm + SM_GATES;
    float* stg   = sm + SM_STAGE;
    float* b0s   = sm + SM_B0;
    float* b1s   = sm + SM_B1;
    float* embr  = sm + SM_EMBR;
    float* embT  = sm + SM_EMBT;
    float* mh1   = sm + SM_MH1;
    float* w1ys  = sm + SM_W1Y;
    float* w3s   = sm + SM_W3;
    float* bm2s  = sm + SM_BM2;
    float* xfT   = sm + SM_XFT;
    float* hes   = sm + SM_HES;
    float* cys   = sm + SM_CY;
    float* ces   = sm + SM_CE;
    float* red   = sm + SM_RED;
    float* a1s   = sm + SM_A1;

    const int tid  = threadIdx.x;
    const int brow = blockIdx.x * RPB;

    // ---- init ----
    for (int i = tid; i < 2048; i += NT) xv[192 + i] = 0.0f;   // h0, h1 = 0
    for (int i = tid; i < 512; i += NT) { b0s[i] = g_b0[i]; b1s[i] = g_b1[i]; }
    for (int i = tid; i < 12800; i += NT) a1s[i] = g_A1t[i];
    if (tid < 128) {
        int r = tid >> 4, k = tid & 15;
        embr[r * 16 + k] = turb_emb[turb_idx[brow + r] * 16 + k];
    }
    if (tid < 128) {
        w1ys[tid] = g_W1T[151 * 128 + tid];
        w3s[tid]  = W3[tid];
        bm2s[tid] = b2m[tid];
    }
    if (tid < 100) { cys[tid] = g_cy[tid]; ces[tid] = g_ce[tid]; }
    __syncthreads();
    if (tid < 128) {
        int k = tid >> 3, r = tid & 7;
        float v = embr[r * 16 + k];
        embT[k * 8 + r] = v;
        xv[(8 + k) * 8 + r] = v;   // constant emb part of in0
    }
    __syncthreads();

    const int g0  = (tid >> 1) << 2;   // 4 gates (lane pairs share weight)
    const int r0g = (tid & 1) << 2;    // 4 rows
    const int uu  = tid & 127;
    const int r0c = (tid >> 7) << 2;   // combine rows

    float c0r[4] = {0.f, 0.f, 0.f, 0.f};
    float c1r[4] = {0.f, 0.f, 0.f, 0.f};

    // x_hist prefetch (one step ahead, registers)
    const int xk = tid & 7, xr = tid >> 3;
    float xnext = 0.f;
    if (tid < 64) xnext = __ldg(&x_hist[((brow + xr) * 96 + 0) * 8 + xk]);

    // =================== LSTM encoder ===================
    for (int t = 0; t < 96; t++) {
        if (tid < 64) {
            xv[xk * 8 + xr] = xnext;   // protected by chunk-0 sync inside lstm_gemm
            if (t + 1 < 96) xnext = __ldg(&x_hist[((brow + xr) * 96 + (t + 1)) * 8 + xk]);
        }
        lstm_gemm(g_W0cat, 152, xv, gates, stg, g0, r0g);
        __syncthreads();               // gates visible for combine
        #pragma unroll
        for (int ri = 0; ri < 4; ri++) {
            int r = r0c + ri;
            float gi = gates[r * 512 + uu]       + b0s[uu];
            float gf = gates[r * 512 + 128 + uu] + b0s[128 + uu];
            float gc = gates[r * 512 + 256 + uu] + b0s[256 + uu];
            float go = gates[r * 512 + 384 + uu] + b0s[384 + uu];
            float cc = sigf(gf) * c0r[ri] + sigf(gi) * tanhf_fast(gc);
            c0r[ri] = cc;
            xv[(24 + uu) * 8 + r] = sigf(go) * tanhf_fast(cc);
        }
        lstm_gemm(g_W1cat, 256, xv + 24 * 8, gates, stg, g0, r0g);
        __syncthreads();               // gates visible for combine
        #pragma unroll
        for (int ri = 0; ri < 4; ri++) {
            int r = r0c + ri;
            float gi = gates[r * 512 + uu]       + b1s[uu];
            float gf = gates[r * 512 + 128 + uu] + b1s[128 + uu];
            float gc = gates[r * 512 + 256 + uu] + b1s[256 + uu];
            float go = gates[r * 512 + 384 + uu] + b1s[384 + uu];
            float cc = sigf(gf) * c1r[ri] + sigf(gi) * tanhf_fast(gc);
            c1r[ri] = cc;
            xv[(152 + uu) * 8 + r] = sigf(go) * tanhf_fast(cc);
        }
        // h1 writes protected by next step's chunk-0 sync
    }
    __syncthreads();
    // enc_out = xv rows 152..279, layout [128][8]

    // =================== AR + diffusion (two independent halves) ===================
    const int half = tid >> 7;
    const int local = tid & 127;
    const int r0d = half * 4;
    const float b3v = __ldg(&b3p[0]);

    // W2 column in registers: w2r[u] = W2[uu][u]   (no-spill layout)
    float w2r[128];
    #pragma unroll
    for (int u = 0; u < 128; u++) w2r[u] = __ldg(&g_W2s[(u << 7) + uu]);

    const float w1yv = w1ys[uu];
    const float w3v  = w3s[uu];
    const float bm2v = bm2s[uu];
    const ull bm2p = pack2(bm2v, bm2v);

    float ypa[4];
    #pragma unroll
    for (int j = 0; j < 4; j++) ypa[j] = __ldg(&y0[brow + r0d + j]);

    const int wih = (tid >> 5) & 3;
    const int lane = tid & 31;

    for (int p = 0; p < 8; p++) {
        if (local < 24) {
            int k = local >> 2, rl = local & 3;
            xfT[half * 24 + k * 4 + rl] = __ldg(&x_future[(brow + r0d + rl) * 48 + p * 6 + k]);
        }
        if (local < 16) {
            int j = local & 7;
            float f = __expf(-logf(10000.0f) * (float)j / 8.0f);
            float a = (float)p * f;
            hes[half * 16 + local] = (local < 8) ? cosf(a) : sinf(a);
        }
        float yra[4];
        #pragma unroll
        for (int j = 0; j < 4; j++) yra[j] = __ldg(&init_noise[p * 1024 + brow + r0d + j]);
        barh(half);

        // ---- base (registers) ----
        float4 base = make_float4(0.f, 0.f, 0.f, 0.f);
        {
            #pragma unroll 8
            for (int k = 0; k < 128; k++) {
                float w = __ldg(&g_W1T[(k << 7) + uu]);
                const float4 h = *reinterpret_cast<const float4*>(&xv[(152 + k) * 8 + r0d]);
                base.x += w * h.x; base.y += w * h.y; base.z += w * h.z; base.w += w * h.w;
            }
            #pragma unroll
            for (int k = 0; k < 6; k++) {
                float w = __ldg(&g_W1T[((128 + k) << 7) + uu]);
                const float4 x = *reinterpret_cast<const float4*>(&xfT[half * 24 + k * 4]);
                base.x += w * x.x; base.y += w * x.y; base.z += w * x.z; base.w += w * x.w;
            }
            #pragma unroll
            for (int k = 0; k < 16; k++) {
                float w = __ldg(&g_W1T[((134 + k) << 7) + uu]);
                const float* ep = &embT[k * 8 + r0d];
                base.x += w * ep[0]; base.y += w * ep[1]; base.z += w * ep[2]; base.w += w * ep[3];
            }
            {
                float w = __ldg(&g_W1T[(150 << 7) + uu]);
                base.x += w * ypa[0]; base.y += w * ypa[1]; base.z += w * ypa[2]; base.w += w * ypa[3];
            }
            float hsum = 0.f;
            #pragma unroll
            for (int k = 0; k < 16; k++) hsum += __ldg(&g_W1T[((168 + k) << 7) + uu]) * hes[half * 16 + k];
            float bb = __ldg(&b1m[uu]) + hsum;
            base.x += bb; base.y += bb; base.z += bb; base.w += bb;
        }

        // ---- 100 diffusion steps ----
        for (int tt = 99; tt >= 0; tt--) {
            // stage 1
            {
                float av = a1s[tt * 128 + uu];
                float4 m;
                m.x = fmaxf(base.x + yra[0] * w1yv + av, 0.f);
                m.y = fmaxf(base.y + yra[1] * w1yv + av, 0.f);
                m.z = fmaxf(base.z + yra[2] * w1yv + av, 0.f);
                m.w = fmaxf(base.w + yra[3] * w1yv + av, 0.f);
                *reinterpret_cast<float4*>(&mh1[(uu << 3) + r0d]) = m;
            }
            barh(half);

            // stage 2: f32x2 GEMV
            {
                ull acc01 = bm2p;
                ull acc23 = bm2p;
                #pragma unroll
                for (int u = 0; u < 128; u++) {
                    const ulonglong2 h = *reinterpret_cast<const ulonglong2*>(&mh1[(u << 3) + r0d]);
                    ull dw = dup2(w2r[u]);
                    ffma2(acc01, dw, h.x);
                    ffma2(acc23, dw, h.y);
                }
                float2 a01 = unpack2(acc01);
                float2 a23 = unpack2(acc23);
                float e0 = fmaxf(a01.x, 0.f) * w3v;
                float e1 = fmaxf(a01.y, 0.f) * w3v;
                float e2 = fmaxf(a23.x, 0.f) * w3v;
                float e3 = fmaxf(a23.y, 0.f) * w3v;
                #pragma unroll
                for (int off = 16; off > 0; off >>= 1) {
                    e0 += __shfl_down_sync(0xffffffffu, e0, off);
                    e1 += __shfl_down_sync(0xffffffffu, e1, off);
                    e2 += __shfl_down_sync(0xffffffffu, e2, off);
                    e3 += __shfl_down_sync(0xffffffffu, e3, off);
                }
                if (lane == 0)
                    *reinterpret_cast<float4*>(&red[half * 16 + wih * 4]) = make_float4(e0, e1, e2, e3);
            }
            barh(half);

            // y update (redundant per thread, registers)
            {
                const float4 q0 = *reinterpret_cast<const float4*>(&red[half * 16 + 0]);
                const float4 q1 = *reinterpret_cast<const float4*>(&red[half * 16 + 4]);
                const float4 q2 = *reinterpret_cast<const float4*>(&red[half * 16 + 8]);
                const float4 q3 = *reinterpret_cast<const float4*>(&red[half * 16 + 12]);
                float cy = cys[tt], ce = ces[tt];
                yra[0] = cy * yra[0] - ce * (b3v + q0.x + q1.x + q2.x + q3.x);
                yra[1] = cy * yra[1] - ce * (b3v + q0.y + q1.y + q2.y + q3.y);
                yra[2] = cy * yra[2] - ce * (b3v + q0.z + q1.z + q2.z + q3.z);
                yra[3] = cy * yra[3] - ce * (b3v + q0.w + q1.w + q2.w + q3.w);
            }
        }

        if (local < 4) {
            float v = (local == 0) ? yra[0] : (local == 1) ? yra[1] : (local == 2) ? yra[2] : yra[3];
            out[(brow + r0d + local) * 8 + p] = v;
        }
        #pragma unroll
        for (int j = 0; j < 4; j++) ypa[j] = yra[j];
    }
}

// ---------------- launch ----------------
extern "C" void kernel_launch(void* const* d_in, const int* in_sizes, int n_in,
                              void* d_out, int out_size) {
    const float* x_hist     = (const float*)d_in[0];
    const float* x_future   = (const float*)d_in[1];
    const float* y0         = (const float*)d_in[2];
    const int*   turb_idx   = (const int*)d_in[3];
    const float* init_noise = (const float*)d_in[5];
    const float* turb_emb   = (const float*)d_in[6];
    const float* W_ih0      = (const float*)d_in[7];
    const float* W_hh0      = (const float*)d_in[8];
    const float* b_ih0      = (const float*)d_in[9];
    const float* b_hh0      = (const float*)d_in[10];
    const float* W_ih1      = (const float*)d_in[11];
    const float* W_hh1      = (const float*)d_in[12];
    const float* b_ih1      = (const float*)d_in[13];
    const float* b_hh1      = (const float*)d_in[14];
    const float* W1         = (const float*)d_in[15];
    const float* b1m        = (const float*)d_in[16];
    const float* W2         = (const float*)d_in[17];
    const float* b2m        = (const float*)d_in[18];
    const float* W3         = (const float*)d_in[19];
    const float* b3         = (const float*)d_in[20];
    float* out = (float*)d_out;

    prologue_kernel<<<128, 256>>>(W_ih0, W_hh0, b_ih0, b_hh0,
                                  W_ih1, W_hh1, b_ih1, b_hh1, W1, W2);

    cudaFuncSetAttribute(fused_kernel, cudaFuncAttributeMaxDynamicSharedMemorySize, SMEM_BYTES);
    fused_kernel<<<NBLK, NT, SMEM_BYTES>>>(x_hist, x_future, y0, turb_idx, init_noise,
                                           turb_emb, b1m, b2m, W3, b3, out);
}

// round 12
// speedup vs baseline: 1.8426x; 1.1077x over previous
#include <cuda_runtime.h>
#include <math.h>

#define NT 256
#define RPB 8
#define NBLK 128
#define KC 32
#define KCBYTES (KC * 512 * 4)

typedef unsigned long long ull;

// ---------------- device scratch ----------------
__device__ float g_W0cat[152 * 512];   // [k][g]: rows 0..23 Wih0^T, 24..151 Whh0^T
__device__ float g_W1cat[256 * 512];   // [k][g]: rows 0..127 Wih1^T, 128..255 Whh1^T
__device__ float g_b0[512];
__device__ float g_b1[512];
__device__ float g_W1T[184 * 128];     // [k][u]
__device__ float g_W2s[128 * 128];     // [u][v] = W2[v][u]
__device__ float g_A1t[100 * 128];
__device__ float g_cy[100];
__device__ float g_ce[100];

// ---------------- prologue ----------------
__global__ void prologue_kernel(const float* __restrict__ W_ih0, const float* __restrict__ W_hh0,
                                const float* __restrict__ b_ih0, const float* __restrict__ b_hh0,
                                const float* __restrict__ W_ih1, const float* __restrict__ W_hh1,
                                const float* __restrict__ b_ih1, const float* __restrict__ b_hh1,
                                const float* __restrict__ W1,    const float* __restrict__ W2) {
    int tid = blockIdx.x * blockDim.x + threadIdx.x;
    int nth = gridDim.x * blockDim.x;

    for (int i = tid; i < 24 * 512; i += nth) {
        int k = i >> 9, g = i & 511;
        g_W0cat[i] = W_ih0[g * 24 + k];
    }
    for (int i = tid; i < 128 * 512; i += nth) {
        int k = i >> 9, g = i & 511;
        g_W0cat[(24 + k) * 512 + g]  = W_hh0[g * 128 + k];
        g_W1cat[k * 512 + g]         = W_ih1[g * 128 + k];
        g_W1cat[(128 + k) * 512 + g] = W_hh1[g * 128 + k];
    }
    for (int i = tid; i < 512; i += nth) {
        g_b0[i] = b_ih0[i] + b_hh0[i];
        g_b1[i] = b_ih1[i] + b_hh1[i];
    }
    for (int i = tid; i < 184 * 128; i += nth) {
        int k = i >> 7, u = i & 127;
        g_W1T[i] = W1[u * 184 + k];
    }
    for (int i = tid; i < 128 * 128; i += nth) {
        int u = i >> 7, v = i & 127;
        g_W2s[i] = W2[v * 128 + u];
    }
    for (int i = tid; i < 100 * 128; i += nth) {
        int t = i >> 7, u = i & 127;
        float acc = 0.f;
        #pragma unroll
        for (int j = 0; j < 8; j++) {
            float f = expf(-logf(10000.0f) * (float)j / 8.0f);
            float a = (float)t * f;
            acc += W1[u * 184 + 152 + j] * cosf(a);
            acc += W1[u * 184 + 160 + j] * sinf(a);
        }
        g_A1t[i] = acc;
    }
    if (tid == 0) {
        float ab = 1.0f;
        for (int t = 0; t < 100; t++) {
            float beta  = 1e-4f + (0.02f - 1e-4f) * (float)t / 99.0f;
            float alpha = 1.0f - beta;
            ab *= alpha;
            if (t == 0) {
                float p = sqrtf(ab) + 1e-8f;
                g_cy[0] = 1.0f / p;
                g_ce[0] = sqrtf(1.0f - ab) / p;
            } else {
                float inv = 1.0f / (sqrtf(alpha) + 1e-8f);
                g_cy[t] = inv;
                g_ce[t] = beta / (sqrtf(1.0f - ab) + 1e-8f) * inv;
            }
        }
    }
}

// ---------------- fast math helpers ----------------
__device__ __forceinline__ float sigf(float x) {
    float xc = fminf(fmaxf(x, -30.f), 30.f);
    return __fdividef(1.0f, 1.0f + __expf(-xc));
}
__device__ __forceinline__ float tanhf_fast(float x) {
    float xc = fminf(fmaxf(x, -15.f), 15.f);
    float e = __expf(2.0f * xc);
    return __fdividef(e - 1.0f, e + 1.0f);
}
__device__ __forceinline__ void ffma2(ull &d, ull a, ull b) {
    asm("fma.rn.f32x2 %0, %1, %2, %0;" : "+l"(d) : "l"(a), "l"(b));
}
__device__ __forceinline__ ull dup2(float x) {
    ull r;
    asm("mov.b64 %0, {%1, %1};" : "=l"(r) : "f"(x));
    return r;
}
__device__ __forceinline__ ull pack2(float lo, float hi) {
    ull r;
    asm("mov.b64 %0, {%1, %2};" : "=l"(r) : "f"(lo), "f"(hi));
    return r;
}
__device__ __forceinline__ float2 unpack2(ull v) {
    float2 r;
    asm("mov.b64 {%0, %1}, %2;" : "=f"(r.x), "=f"(r.y) : "l"(v));
    return r;
}
__device__ __forceinline__ unsigned smem_u32(const void* p) {
    unsigned a;
    asm("{ .reg .u64 t; cvta.to.shared.u64 t, %1; cvt.u32.u64 %0, t; }" : "=r"(a) : "l"(p));
    return a;
}

// ---------------- bulk staging (TMA path, 1 instr per chunk) ----------------
__device__ __forceinline__ void bulk_stage(unsigned dst, const float* __restrict__ src,
                                           unsigned bytes, unsigned mbar) {
    asm volatile("mbarrier.arrive.expect_tx.shared.b64 _, [%0], %1;"
                 :: "r"(mbar), "r"(bytes) : "memory");
    asm volatile("cp.async.bulk.shared::cluster.global.mbarrier::complete_tx::bytes [%0], [%1], %2, [%3];"
                 :: "r"(dst), "l"(src), "r"(bytes), "r"(mbar) : "memory");
}
__device__ __forceinline__ void mbar_wait(unsigned mbar, int phase) {
    asm volatile(
        "{\n\t.reg .pred P1;\n\t"
        "WAIT_LOOP_%=:\n\t"
        "mbarrier.try_wait.parity.shared.b64 P1, [%0], %1;\n\t"
        "@P1 bra.uni WAIT_DONE_%=;\n\t"
        "bra.uni WAIT_LOOP_%=;\n\t"
        "WAIT_DONE_%=:\n\t}"
        :: "r"(mbar), "r"(phase) : "memory");
}

// ---------------- smem layout (floats) ----------------
#define SM_XV     0        // [280][8]: rows 0..7 x_t, 8..23 emb, 24..151 h0, 152..279 h1
#define SM_GATES  2240     // [8][512]
#define SM_STAGE  6336     // 2 x (KC*512) = 32768 (byte offset 25344, 16B-aligned)
#define SM_B0     39104    // 512
#define SM_B1     39616    // 512
#define SM_EMBR   40128    // [8][16]
#define SM_EMBT   40256    // [16][8]
#define SM_MH1    40384    // [128][8]
#define SM_W1Y    41408    // 128
#define SM_W3     41536    // 128
#define SM_BM2    41664    // 128
#define SM_XFT    41792    // 48
#define SM_HES    41840    // 32
#define SM_CY     41872    // 100
#define SM_CE     41972    // 100
#define SM_RED    42072    // 32
#define SM_A1     42112    // 12800
#define SM_MB     54912    // 2 mbarriers (4 floats, 8B-aligned)
#define SM_TOTAL  54916
#define SMEM_BYTES (SM_TOTAL * 4)

__device__ __forceinline__ void barh(int half) {
    asm volatile("bar.sync %0, 128;" :: "r"(half + 1) : "memory");
}

// ---------------- LSTM GEMM: bulk-staged double buffer, 1 sync per chunk ----------------
// Caller must __syncthreads() before reading gates (no trailing sync).
__device__ __forceinline__ void lstm_gemm(const float* __restrict__ gW, int K,
                                          const float* __restrict__ xv, float* gates,
                                          float* stg, unsigned stg_u32,
                                          unsigned mb0, unsigned mb1, int &ph0, int &ph1,
                                          int g0, int r0g, int tid) {
    ull a00 = 0, a01 = 0, a10 = 0, a11 = 0, a20 = 0, a21 = 0, a30 = 0, a31 = 0;

    const int NC = (K + KC - 1) / KC;
    if (tid == 0) {
        int kc0 = (K < KC) ? K : KC;
        bulk_stage(stg_u32, gW, (unsigned)(kc0 * 512 * 4), mb0);
    }

    #pragma unroll 1
    for (int c = 0; c < NC; c++) {
        // wait for chunk c's bulk copy
        unsigned mcur = (c & 1) ? mb1 : mb0;
        int pcur = (c & 1) ? ph1 : ph0;
        mbar_wait(mcur, pcur);
        if (c & 1) ph1 ^= 1; else ph0 ^= 1;
        __syncthreads();   // all threads past wait AND done computing chunk c-1

        // issue chunk c+1 into the buffer freed by chunk c-1
        if (c + 1 < NC && tid == 0) {
            int kn = K - (c + 1) * KC; if (kn > KC) kn = KC;
            unsigned mnx = ((c + 1) & 1) ? mb1 : mb0;
            bulk_stage(stg_u32 + ((c + 1) & 1) * KCBYTES,
                       gW + (c + 1) * KC * 512, (unsigned)(kn * 512 * 4), mnx);
        }

        const float* buf = stg + (c & 1) * (KC * 512);
        const int kbase = c * KC;
        int kc = K - kbase; if (kc > KC) kc = KC;

        #pragma unroll 8
        for (int kk = 0; kk < kc; kk++) {
            const ulonglong2 w = *reinterpret_cast<const ulonglong2*>(buf + (kk << 9) + g0);
            const float4 x = *reinterpret_cast<const float4*>(xv + ((kbase + kk) << 3) + r0g);
            ull d0 = dup2(x.x), d1 = dup2(x.y), d2 = dup2(x.z), d3 = dup2(x.w);
            ffma2(a00, w.x, d0); ffma2(a01, w.y, d0);
            ffma2(a10, w.x, d1); ffma2(a11, w.y, d1);
            ffma2(a20, w.x, d2); ffma2(a21, w.y, d2);
            ffma2(a30, w.x, d3); ffma2(a31, w.y, d3);
        }

        if (c == NC - 1) {
            *reinterpret_cast<ulonglong2*>(&gates[(r0g    ) * 512 + g0]) = make_ulonglong2(a00, a01);
            *reinterpret_cast<ulonglong2*>(&gates[(r0g + 1) * 512 + g0]) = make_ulonglong2(a10, a11);
            *reinterpret_cast<ulonglong2*>(&gates[(r0g + 2) * 512 + g0]) = make_ulonglong2(a20, a21);
            *reinterpret_cast<ulonglong2*>(&gates[(r0g + 3) * 512 + g0]) = make_ulonglong2(a30, a31);
        }
    }
}

// ---------------- main fused kernel ----------------
__global__ __launch_bounds__(NT, 1)
void fused_kernel(const float* __restrict__ x_hist, const float* __restrict__ x_future,
                  const float* __restrict__ y0, const int* __restrict__ turb_idx,
                  const float* __restrict__ init_noise, const float* __restrict__ turb_emb,
                  const float* __restrict__ b1m, const float* __restrict__ b2m,
                  const float* __restrict__ W3, const float* __restrict__ b3p,
                  float* __restrict__ out) {
    extern __shared__ float sm[];
    float* xv    = sm + SM_XV;
    float* gates = sm + SM_GATES;
    float* stg   = sm + SM_STAGE;
    float* b0s   = sm + SM_B0;
    float* b1s   = sm + SM_B1;
    float* embr  = sm + SM_EMBR;
    float* embT  = sm + SM_EMBT;
    float* mh1   = sm + SM_MH1;
    float* w1ys  = sm + SM_W1Y;
    float* w3s   = sm + SM_W3;
    float* bm2s  = sm + SM_BM2;
    float* xfT   = sm + SM_XFT;
    float* hes   = sm + SM_HES;
    float* cys   = sm + SM_CY;
    float* ces   = sm + SM_CE;
    float* red   = sm + SM_RED;
    float* a1s   = sm + SM_A1;

    const int tid  = threadIdx.x;
    const int brow = blockIdx.x * RPB;

    const unsigned stg_u32 = smem_u32(stg);
    const unsigned mb0 = smem_u32(sm + SM_MB);
    const unsigned mb1 = mb0 + 8;

    // ---- init ----
    for (int i = tid; i < 2048; i += NT) xv[192 + i] = 0.0f;   // h0, h1 = 0
    for (int i = tid; i < 512; i += NT) { b0s[i] = g_b0[i]; b1s[i] = g_b1[i]; }
    for (int i = tid; i < 12800; i += NT) a1s[i] = g_A1t[i];
    if (tid < 128) {
        int r = tid >> 4, k = tid & 15;
        embr[r * 16 + k] = turb_emb[turb_idx[brow + r] * 16 + k];
    }
    if (tid < 128) {
        w1ys[tid] = g_W1T[151 * 128 + tid];
        w3s[tid]  = W3[tid];
        bm2s[tid] = b2m[tid];
    }
    if (tid < 100) { cys[tid] = g_cy[tid]; ces[tid] = g_ce[tid]; }
    if (tid == 0) {
        asm volatile("mbarrier.init.shared.b64 [%0], 1;" :: "r"(mb0) : "memory");
        asm volatile("mbarrier.init.shared.b64 [%0], 1;" :: "r"(mb1) : "memory");
    }
    __syncthreads();
    if (tid < 128) {
        int k = tid >> 3, r = tid & 7;
        float v = embr[r * 16 + k];
        embT[k * 8 + r] = v;
        xv[(8 + k) * 8 + r] = v;   // constant emb part of in0
    }
    __syncthreads();

    const int g0  = (tid >> 1) << 2;   // 4 gates (lane pairs share weight)
    const int r0g = (tid & 1) << 2;    // 4 rows
    const int uu  = tid & 127;
    const int r0c = (tid >> 7) << 2;   // combine rows

    float c0r[4] = {0.f, 0.f, 0.f, 0.f};
    float c1r[4] = {0.f, 0.f, 0.f, 0.f};
    int ph0 = 0, ph1 = 0;

    // x_hist prefetch (one step ahead, registers)
    const int xk = tid & 7, xr = tid >> 3;
    float xnext = 0.f;
    if (tid < 64) xnext = __ldg(&x_hist[((brow + xr) * 96 + 0) * 8 + xk]);

    // =================== LSTM encoder ===================
    for (int t = 0; t < 96; t++) {
        if (tid < 64) {
            xv[xk * 8 + xr] = xnext;   // protected by chunk-0 sync inside lstm_gemm
            if (t + 1 < 96) xnext = __ldg(&x_hist[((brow + xr) * 96 + (t + 1)) * 8 + xk]);
        }
        lstm_gemm(g_W0cat, 152, xv, gates, stg, stg_u32, mb0, mb1, ph0, ph1, g0, r0g, tid);
        __syncthreads();               // gates visible for combine
        #pragma unroll
        for (int ri = 0; ri < 4; ri++) {
            int r = r0c + ri;
            float gi = gates[r * 512 + uu]       + b0s[uu];
            float gf = gates[r * 512 + 128 + uu] + b0s[128 + uu];
            float gc = gates[r * 512 + 256 + uu] + b0s[256 + uu];
            float go = gates[r * 512 + 384 + uu] + b0s[384 + uu];
            float cc = sigf(gf) * c0r[ri] + sigf(gi) * tanhf_fast(gc);
            c0r[ri] = cc;
            xv[(24 + uu) * 8 + r] = sigf(go) * tanhf_fast(cc);
        }
        lstm_gemm(g_W1cat, 256, xv + 24 * 8, gates, stg, stg_u32, mb0, mb1, ph0, ph1, g0, r0g, tid);
        __syncthreads();               // gates visible for combine
        #pragma unroll
        for (int ri = 0; ri < 4; ri++) {
            int r = r0c + ri;
            float gi = gates[r * 512 + uu]       + b1s[uu];
            float gf = gates[r * 512 + 128 + uu] + b1s[128 + uu];
            float gc = gates[r * 512 + 256 + uu] + b1s[256 + uu];
            float go = gates[r * 512 + 384 + uu] + b1s[384 + uu];
            float cc = sigf(gf) * c1r[ri] + sigf(gi) * tanhf_fast(gc);
            c1r[ri] = cc;
            xv[(152 + uu) * 8 + r] = sigf(go) * tanhf_fast(cc);
        }
        // h1 writes protected by next step's chunk-0 sync
    }
    __syncthreads();
    // enc_out = xv rows 152..279, layout [128][8]

    // =================== AR + diffusion (two independent halves) ===================
    const int half = tid >> 7;
    const int local = tid & 127;
    const int r0d = half * 4;
    const float b3v = __ldg(&b3p[0]);

    // W2 column in registers: w2r[u] = W2[uu][u]   (no-spill layout)
    float w2r[128];
    #pragma unroll
    for (int u = 0; u < 128; u++) w2r[u] = __ldg(&g_W2s[(u << 7) + uu]);

    const float w1yv = w1ys[uu];
    const float w3v  = w3s[uu];
    const float bm2v = bm2s[uu];
    const ull bm2p = pack2(bm2v, bm2v);

    float ypa[4];
    #pragma unroll
    for (int j = 0; j < 4; j++) ypa[j] = __ldg(&y0[brow + r0d + j]);

    const int wih = (tid >> 5) & 3;
    const int lane = tid & 31;

    for (int p = 0; p < 8; p++) {
        if (local < 24) {
            int k = local >> 2, rl = local & 3;
            xfT[half * 24 + k * 4 + rl] = __ldg(&x_future[(brow + r0d + rl) * 48 + p * 6 + k]);
        }
        if (local < 16) {
            int j = local & 7;
            float f = __expf(-logf(10000.0f) * (float)j / 8.0f);
            float a = (float)p * f;
            hes[half * 16 + local] = (local < 8) ? cosf(a) : sinf(a);
        }
        float yra[4];
        #pragma unroll
        for (int j = 0; j < 4; j++) yra[j] = __ldg(&init_noise[p * 1024 + brow + r0d + j]);
        barh(half);

        // ---- base (registers) ----
        float4 base = make_float4(0.f, 0.f, 0.f, 0.f);
        {
            #pragma unroll 8
            for (int k = 0; k < 128; k++) {
                float w = __ldg(&g_W1T[(k << 7) + uu]);
                const float4 h = *reinterpret_cast<const float4*>(&xv[(152 + k) * 8 + r0d]);
                base.x += w * h.x; base.y += w * h.y; base.z += w * h.z; base.w += w * h.w;
            }
            #pragma unroll
            for (int k = 0; k < 6; k++) {
                float w = __ldg(&g_W1T[((128 + k) << 7) + uu]);
                const float4 x = *reinterpret_cast<const float4*>(&xfT[half * 24 + k * 4]);
                base.x += w * x.x; base.y += w * x.y; base.z += w * x.z; base.w += w * x.w;
            }
            #pragma unroll
            for (int k = 0; k < 16; k++) {
                float w = __ldg(&g_W1T[((134 + k) << 7) + uu]);
                const float* ep = &embT[k * 8 + r0d];
                base.x += w * ep[0]; base.y += w * ep[1]; base.z += w * ep[2]; base.w += w * ep[3];
            }
            {
                float w = __ldg(&g_W1T[(150 << 7) + uu]);
                base.x += w * ypa[0]; base.y += w * ypa[1]; base.z += w * ypa[2]; base.w += w * ypa[3];
            }
            float hsum = 0.f;
            #pragma unroll
            for (int k = 0; k < 16; k++) hsum += __ldg(&g_W1T[((168 + k) << 7) + uu]) * hes[half * 16 + k];
            float bb = __ldg(&b1m[uu]) + hsum;
            base.x += bb; base.y += bb; base.z += bb; base.w += bb;
        }

        // ---- 100 diffusion steps ----
        for (int tt = 99; tt >= 0; tt--) {
            // stage 1
            {
                float av = a1s[tt * 128 + uu];
                float4 m;
                m.x = fmaxf(base.x + yra[0] * w1yv + av, 0.f);
                m.y = fmaxf(base.y + yra[1] * w1yv + av, 0.f);
                m.z = fmaxf(base.z + yra[2] * w1yv + av, 0.f);
                m.w = fmaxf(base.w + yra[3] * w1yv + av, 0.f);
                *reinterpret_cast<float4*>(&mh1[(uu << 3) + r0d]) = m;
            }
            barh(half);

            // stage 2: f32x2 GEMV
            {
                ull acc01 = bm2p;
                ull acc23 = bm2p;
                #pragma unroll
                for (int u = 0; u < 128; u++) {
                    const ulonglong2 h = *reinterpret_cast<const ulonglong2*>(&mh1[(u << 3) + r0d]);
                    ull dw = dup2(w2r[u]);
                    ffma2(acc01, dw, h.x);
                    ffma2(acc23, dw, h.y);
                }
                float2 a01 = unpack2(acc01);
                float2 a23 = unpack2(acc23);
                float e0 = fmaxf(a01.x, 0.f) * w3v;
                float e1 = fmaxf(a01.y, 0.f) * w3v;
                float e2 = fmaxf(a23.x, 0.f) * w3v;
                float e3 = fmaxf(a23.y, 0.f) * w3v;
                #pragma unroll
                for (int off = 16; off > 0; off >>= 1) {
                    e0 += __shfl_down_sync(0xffffffffu, e0, off);
                    e1 += __shfl_down_sync(0xffffffffu, e1, off);
                    e2 += __shfl_down_sync(0xffffffffu, e2, off);
                    e3 += __shfl_down_sync(0xffffffffu, e3, off);
                }
                if (lane == 0)
                    *reinterpret_cast<float4*>(&red[half * 16 + wih * 4]) = make_float4(e0, e1, e2, e3);
            }
            barh(half);

            // y update (redundant per thread, registers)
            {
                const float4 q0 = *reinterpret_cast<const float4*>(&red[half * 16 + 0]);
                const float4 q1 = *reinterpret_cast<const float4*>(&red[half * 16 + 4]);
                const float4 q2 = *reinterpret_cast<const float4*>(&red[half * 16 + 8]);
                const float4 q3 = *reinterpret_cast<const float4*>(&red[half * 16 + 12]);
                float cy = cys[tt], ce = ces[tt];
                yra[0] = cy * yra[0] - ce * (b3v + q0.x + q1.x + q2.x + q3.x);
                yra[1] = cy * yra[1] - ce * (b3v + q0.y + q1.y + q2.y + q3.y);
                yra[2] = cy * yra[2] - ce * (b3v + q0.z + q1.z + q2.z + q3.z);
                yra[3] = cy * yra[3] - ce * (b3v + q0.w + q1.w + q2.w + q3.w);
            }
        }

        if (local < 4) {
            float v = (local == 0) ? yra[0] : (local == 1) ? yra[1] : (local == 2) ? yra[2] : yra[3];
            out[(brow + r0d + local) * 8 + p] = v;
        }
        #pragma unroll
        for (int j = 0; j < 4; j++) ypa[j] = yra[j];
    }
}

// ---------------- launch ----------------
extern "C" void kernel_launch(void* const* d_in, const int* in_sizes, int n_in,
                              void* d_out, int out_size) {
    const float* x_hist     = (const float*)d_in[0];
    const float* x_future   = (const float*)d_in[1];
    const float* y0         = (const float*)d_in[2];
    const int*   turb_idx   = (const int*)d_in[3];
    const float* init_noise = (const float*)d_in[5];
    const float* turb_emb   = (const float*)d_in[6];
    const float* W_ih0      = (const float*)d_in[7];
    const float* W_hh0      = (const float*)d_in[8];
    const float* b_ih0      = (const float*)d_in[9];
    const float* b_hh0      = (const float*)d_in[10];
    const float* W_ih1      = (const float*)d_in[11];
    const float* W_hh1      = (const float*)d_in[12];
    const float* b_ih1      = (const float*)d_in[13];
    const float* b_hh1      = (const float*)d_in[14];
    const float* W1         = (const float*)d_in[15];
    const float* b1m        = (const float*)d_in[16];
    const float* W2         = (const float*)d_in[17];
    const float* b2m        = (const float*)d_in[18];
    const float* W3         = (const float*)d_in[19];
    const float* b3         = (const float*)d_in[20];
    float* out = (float*)d_out;

    prologue_kernel<<<128, 256>>>(W_ih0, W_hh0, b_ih0, b_hh0,
                                  W_ih1, W_hh1, b_ih1, b_hh1, W1, W2);

    cudaFuncSetAttribute(fused_kernel, cudaFuncAttributeMaxDynamicSharedMemorySize, SMEM_BYTES);
    fused_kernel<<<NBLK, NT, SMEM_BYTES>>>(x_hist, x_future, y0, turb_idx, init_noise,
                                           turb_emb, b1m, b2m, W3, b3, out);
}